// round 1
// baseline (speedup 1.0000x reference)
#include <cuda_runtime.h>
#include <math.h>
#include <stdint.h>
#include <stddef.h>

#define BATCH 4
#define SEQ 1024
#define DMODEL 1024
#define NH 16
#define HD 64
#define NROWS (BATCH*SEQ)          // 4096

// Scratch (static device globals: allowed; no runtime allocation)
__device__ float g_qp[NROWS*DMODEL];
__device__ float g_kp[NROWS*DMODEL];
__device__ float g_vp[NROWS*DMODEL];
__device__ float g_ctx[NROWS*DMODEL];

// ---------------------------------------------------------------------------
// 128x128x8 SGEMM-NT tile:  C[row0+.., col0+..] = alpha * A(MxK) * B(NxK)^T (+bias)
// A row-major lda, B row-major ldb (both read along K contiguously).
// 256 threads, 8x8 per-thread microtile.
// ---------------------------------------------------------------------------
__device__ __forceinline__ void gemm_nt_128(
    const float* __restrict__ A, int lda,
    const float* __restrict__ Bm, int ldb,
    float* __restrict__ C, int ldc,
    int K, float alpha, const float* __restrict__ bias,
    int row0, int col0)
{
    __shared__ float As[8][128];
    __shared__ float Bs[8][128];

    const int tid = threadIdx.x;
    const int tx = tid & 15;        // 0..15
    const int ty = tid >> 4;        // 0..15
    const int tm = ty * 8;
    const int tn = tx * 8;
    const int lm = tid >> 1;        // 0..127
    const int lk = (tid & 1) * 4;   // 0 or 4

    float acc[8][8];
#pragma unroll
    for (int i = 0; i < 8; i++)
#pragma unroll
        for (int j = 0; j < 8; j++) acc[i][j] = 0.f;

    const float* Arow = A + (size_t)(row0 + lm) * lda + lk;
    const float* Brow = Bm + (size_t)(col0 + lm) * ldb + lk;

    for (int k0 = 0; k0 < K; k0 += 8) {
        float4 av = *(const float4*)(Arow + k0);
        float4 bv = *(const float4*)(Brow + k0);
        As[lk + 0][lm] = av.x; As[lk + 1][lm] = av.y;
        As[lk + 2][lm] = av.z; As[lk + 3][lm] = av.w;
        Bs[lk + 0][lm] = bv.x; Bs[lk + 1][lm] = bv.y;
        Bs[lk + 2][lm] = bv.z; Bs[lk + 3][lm] = bv.w;
        __syncthreads();

#pragma unroll
        for (int kk = 0; kk < 8; kk++) {
            float4 a0 = *(const float4*)&As[kk][tm];
            float4 a1 = *(const float4*)&As[kk][tm + 4];
            float4 b0 = *(const float4*)&Bs[kk][tn];
            float4 b1 = *(const float4*)&Bs[kk][tn + 4];
            float a[8] = {a0.x, a0.y, a0.z, a0.w, a1.x, a1.y, a1.z, a1.w};
            float b[8] = {b0.x, b0.y, b0.z, b0.w, b1.x, b1.y, b1.z, b1.w};
#pragma unroll
            for (int i = 0; i < 8; i++)
#pragma unroll
                for (int j = 0; j < 8; j++)
                    acc[i][j] = fmaf(a[i], b[j], acc[i][j]);
        }
        __syncthreads();
    }

#pragma unroll
    for (int i = 0; i < 8; i++) {
        float* crow = C + (size_t)(row0 + tm + i) * ldc + col0 + tn;
#pragma unroll
        for (int j = 0; j < 8; j++) {
            float bb = bias ? bias[col0 + tn + j] : 0.f;
            crow[j] = fmaf(alpha, acc[i][j], bb);
        }
    }
}

// ---------------------------------------------------------------------------
// Projections: qp = q @ Wq^T + bq  (and k, v);  z selects which.
// ---------------------------------------------------------------------------
__global__ void proj_kernel(
    const float* __restrict__ q, const float* __restrict__ k, const float* __restrict__ v,
    const float* __restrict__ Wq, const float* __restrict__ bq,
    const float* __restrict__ Wk, const float* __restrict__ bk,
    const float* __restrict__ Wv, const float* __restrict__ bv)
{
    const float *X, *W, *bias; float* O;
    if (blockIdx.z == 0)      { X = q; W = Wq; bias = bq; O = g_qp; }
    else if (blockIdx.z == 1) { X = k; W = Wk; bias = bk; O = g_kp; }
    else                      { X = v; W = Wv; bias = bv; O = g_vp; }
    gemm_nt_128(X, DMODEL, W, DMODEL, O, DMODEL, DMODEL, 1.f, bias,
                blockIdx.y * 128, blockIdx.x * 128);
}

// ---------------------------------------------------------------------------
// Scores: S[b,h] = (qh @ kh^T) / 8, written directly into attention output.
// ---------------------------------------------------------------------------
__global__ void scores_kernel(float* __restrict__ att)
{
    int z = blockIdx.z;             // b*16 + h
    int b = z >> 4, h = z & 15;
    const float* A  = g_qp + (size_t)b * SEQ * DMODEL + h * HD;
    const float* Bm = g_kp + (size_t)b * SEQ * DMODEL + h * HD;
    float* C = att + (size_t)z * SEQ * SEQ;
    gemm_nt_128(A, DMODEL, Bm, DMODEL, C, SEQ, HD, 0.125f, nullptr,
                blockIdx.y * 128, blockIdx.x * 128);
}

// ---------------------------------------------------------------------------
// Row softmax, in place on the attention buffer. Mask applied (-inf).
// One block (256 threads) per row of 1024; each thread handles one float4.
// ---------------------------------------------------------------------------
__global__ void softmax_kernel(float* __restrict__ att,
                               const unsigned char* __restrict__ masks)
{
    __shared__ float red[8];
    __shared__ float bval;

    int row = blockIdx.x;                    // 0..65535  = ((b*16)+h)*1024 + i
    int b = row >> 14;
    int i = row & (SEQ - 1);
    float* p = att + (size_t)row * SEQ;
    const unsigned char* mrow = masks + ((size_t)b * SEQ + i) * SEQ;

    int j = threadIdx.x * 4;
    float4 s = *(const float4*)(p + j);
    uchar4 m = *(const uchar4*)(mrow + j);
    float v0 = m.x ? -INFINITY : s.x;
    float v1 = m.y ? -INFINITY : s.y;
    float v2 = m.z ? -INFINITY : s.z;
    float v3 = m.w ? -INFINITY : s.w;

    // --- max ---
    float mx = fmaxf(fmaxf(v0, v1), fmaxf(v2, v3));
#pragma unroll
    for (int o = 16; o; o >>= 1) mx = fmaxf(mx, __shfl_xor_sync(0xffffffffu, mx, o));
    if ((threadIdx.x & 31) == 0) red[threadIdx.x >> 5] = mx;
    __syncthreads();
    if (threadIdx.x == 0) {
        float t = red[0];
#pragma unroll
        for (int w = 1; w < 8; w++) t = fmaxf(t, red[w]);
        bval = t;
    }
    __syncthreads();
    float rowmax = bval;

    float e0 = expf(v0 - rowmax);
    float e1 = expf(v1 - rowmax);
    float e2 = expf(v2 - rowmax);
    float e3 = expf(v3 - rowmax);

    // --- sum ---
    float sm = e0 + e1 + e2 + e3;
#pragma unroll
    for (int o = 16; o; o >>= 1) sm += __shfl_xor_sync(0xffffffffu, sm, o);
    __syncthreads();
    if ((threadIdx.x & 31) == 0) red[threadIdx.x >> 5] = sm;
    __syncthreads();
    if (threadIdx.x == 0) {
        float t = 0.f;
#pragma unroll
        for (int w = 0; w < 8; w++) t += red[w];
        bval = 1.0f / t;
    }
    __syncthreads();
    float inv = bval;

    float4 r = make_float4(e0 * inv, e1 * inv, e2 * inv, e3 * inv);
    *(float4*)(p + j) = r;
}

// ---------------------------------------------------------------------------
// ctx[b,:,h] = A[b,h] @ vh[b,h]   (NN GEMM, M=1024, N=64, K=1024)
// 128x64x8 tile, 256 threads, 8x4 per-thread microtile.
// ---------------------------------------------------------------------------
__global__ void av_kernel(const float* __restrict__ att)
{
    __shared__ float As[8][128];
    __shared__ float Bs[8][64];

    int z = blockIdx.z;
    int b = z >> 4, h = z & 15;
    const float* A = att + (size_t)z * SEQ * SEQ;
    const float* V = g_vp + (size_t)b * SEQ * DMODEL + h * HD;
    float* C = g_ctx + (size_t)b * SEQ * DMODEL + h * HD;
    int row0 = blockIdx.y * 128;

    const int tid = threadIdx.x;
    const int tx = tid & 15, ty = tid >> 4;
    const int tm = ty * 8, tn = tx * 4;
    const int lm = tid >> 1, lk = (tid & 1) * 4;
    const int bkk = tid >> 4, bn = (tid & 15) * 4;   // B-loader (tid<128)

    float acc[8][4];
#pragma unroll
    for (int i = 0; i < 8; i++)
#pragma unroll
        for (int j = 0; j < 4; j++) acc[i][j] = 0.f;

    const float* Arow = A + (size_t)(row0 + lm) * SEQ + lk;

    for (int k0 = 0; k0 < SEQ; k0 += 8) {
        float4 av4 = *(const float4*)(Arow + k0);
        As[lk + 0][lm] = av4.x; As[lk + 1][lm] = av4.y;
        As[lk + 2][lm] = av4.z; As[lk + 3][lm] = av4.w;
        if (tid < 128) {
            float4 bv = *(const float4*)(V + (size_t)(k0 + bkk) * DMODEL + bn);
            *(float4*)&Bs[bkk][bn] = bv;
        }
        __syncthreads();
#pragma unroll
        for (int kk = 0; kk < 8; kk++) {
            float4 a0 = *(const float4*)&As[kk][tm];
            float4 a1 = *(const float4*)&As[kk][tm + 4];
            float4 b0 = *(const float4*)&Bs[kk][tn];
            float a[8] = {a0.x, a0.y, a0.z, a0.w, a1.x, a1.y, a1.z, a1.w};
            float bb[4] = {b0.x, b0.y, b0.z, b0.w};
#pragma unroll
            for (int i = 0; i < 8; i++)
#pragma unroll
                for (int j = 0; j < 4; j++)
                    acc[i][j] = fmaf(a[i], bb[j], acc[i][j]);
        }
        __syncthreads();
    }

#pragma unroll
    for (int i = 0; i < 8; i++) {
        float* crow = C + (size_t)(row0 + tm + i) * DMODEL + tn;
#pragma unroll
        for (int j = 0; j < 4; j++) crow[j] = acc[i][j];
    }
}

// ---------------------------------------------------------------------------
// output = LayerNorm(qp + ctx) * g + b.  One block per row of 1024.
// ---------------------------------------------------------------------------
__global__ void ln_kernel(float* __restrict__ out,
                          const float* __restrict__ gam,
                          const float* __restrict__ bet)
{
    __shared__ float reds[8];
    __shared__ float redq[8];
    __shared__ float stat[2];

    int row = blockIdx.x;
    const float* xq = g_qp + (size_t)row * DMODEL;
    const float* xc = g_ctx + (size_t)row * DMODEL;
    int j = threadIdx.x * 4;

    float4 a = *(const float4*)(xq + j);
    float4 c = *(const float4*)(xc + j);
    float x0 = a.x + c.x, x1 = a.y + c.y, x2 = a.z + c.z, x3 = a.w + c.w;

    float s = x0 + x1 + x2 + x3;
    float sq = x0 * x0 + x1 * x1 + x2 * x2 + x3 * x3;
#pragma unroll
    for (int o = 16; o; o >>= 1) {
        s += __shfl_xor_sync(0xffffffffu, s, o);
        sq += __shfl_xor_sync(0xffffffffu, sq, o);
    }
    if ((threadIdx.x & 31) == 0) { reds[threadIdx.x >> 5] = s; redq[threadIdx.x >> 5] = sq; }
    __syncthreads();
    if (threadIdx.x == 0) {
        float S = 0.f, Q = 0.f;
#pragma unroll
        for (int w = 0; w < 8; w++) { S += reds[w]; Q += redq[w]; }
        float mu = S * (1.0f / DMODEL);
        float var = Q * (1.0f / DMODEL) - mu * mu;
        stat[0] = mu;
        stat[1] = rsqrtf(var + 1e-6f);
    }
    __syncthreads();
    float mu = stat[0], r = stat[1];

    float4 g4 = *(const float4*)(gam + j);
    float4 b4 = *(const float4*)(bet + j);
    float4 o4;
    o4.x = (x0 - mu) * r * g4.x + b4.x;
    o4.y = (x1 - mu) * r * g4.y + b4.y;
    o4.z = (x2 - mu) * r * g4.z + b4.z;
    o4.w = (x3 - mu) * r * g4.w + b4.w;
    *(float4*)(out + (size_t)row * DMODEL + j) = o4;
}

// ---------------------------------------------------------------------------
extern "C" void kernel_launch(void* const* d_in, const int* in_sizes, int n_in,
                              void* d_out, int out_size)
{
    const float* q  = (const float*)d_in[0];
    const float* k  = (const float*)d_in[1];
    const float* v  = (const float*)d_in[2];
    const unsigned char* masks = (const unsigned char*)d_in[3];
    const float* Wq = (const float*)d_in[4];
    const float* bq = (const float*)d_in[5];
    const float* Wk = (const float*)d_in[6];
    const float* bk = (const float*)d_in[7];
    const float* Wv = (const float*)d_in[8];
    const float* bv = (const float*)d_in[9];
    const float* lng = (const float*)d_in[10];
    const float* lnb = (const float*)d_in[11];

    float* out = (float*)d_out;
    float* att = out + (size_t)BATCH * SEQ * DMODEL;   // attention region

    proj_kernel<<<dim3(8, 32, 3), 256>>>(q, k, v, Wq, bq, Wk, bk, Wv, bv);
    scores_kernel<<<dim3(8, 8, 64), 256>>>(att);
    softmax_kernel<<<BATCH * NH * SEQ, 256>>>(att, masks);
    av_kernel<<<dim3(1, 8, 64), 256>>>(att);
    ln_kernel<<<NROWS, 256>>>(out, lng, lnb);
}

// round 4
// speedup vs baseline: 2.4679x; 2.4679x over previous
#include <cuda_runtime.h>
#include <cuda_bf16.h>
#include <math.h>
#include <stdint.h>
#include <stddef.h>

#define BATCH 4
#define SEQ 1024
#define DMODEL 1024
#define NH 16
#define HD 64
#define NROWS (BATCH*SEQ)          // 4096

#define PITCH 40                   // bf16 row pitch for 32-wide K tiles (80B, conflict-free)
#define PITCHV 72                  // bf16 row pitch for 64-wide V tiles (144B)

// Scratch (static device globals: allowed; no runtime allocation)
__device__ float g_qp[NROWS*DMODEL];
__device__ float g_kp[NROWS*DMODEL];
__device__ float g_vp[NROWS*DMODEL];
__device__ float g_ctx[NROWS*DMODEL];

// ---------------------------------------------------------------------------
// Baseline-ISA tensor-core helpers (sm_80-level: ldmatrix + mma.sync bf16)
// ---------------------------------------------------------------------------
__device__ __forceinline__ uint32_t cvta_s(const void* p) {
    return (uint32_t)__cvta_generic_to_shared(p);
}

__device__ __forceinline__ void ldsm4(uint32_t* r, uint32_t addr) {
    asm volatile("ldmatrix.sync.aligned.m8n8.x4.shared.b16 {%0,%1,%2,%3}, [%4];"
                 : "=r"(r[0]), "=r"(r[1]), "=r"(r[2]), "=r"(r[3]) : "r"(addr));
}

__device__ __forceinline__ void ldsm4t(uint32_t* r, uint32_t addr) {
    asm volatile("ldmatrix.sync.aligned.m8n8.x4.trans.shared.b16 {%0,%1,%2,%3}, [%4];"
                 : "=r"(r[0]), "=r"(r[1]), "=r"(r[2]), "=r"(r[3]) : "r"(addr));
}

__device__ __forceinline__ void mma_bf16(float* c, const uint32_t* a, const uint32_t* b) {
    asm volatile(
        "mma.sync.aligned.m16n8k16.row.col.f32.bf16.bf16.f32 "
        "{%0,%1,%2,%3}, {%4,%5,%6,%7}, {%8,%9}, {%0,%1,%2,%3};"
        : "+f"(c[0]), "+f"(c[1]), "+f"(c[2]), "+f"(c[3])
        : "r"(a[0]), "r"(a[1]), "r"(a[2]), "r"(a[3]), "r"(b[0]), "r"(b[1]));
}

// bf16x3 split: pack (x,y) into hi bf16x2 and lo bf16x2 (lo = residual)
__device__ __forceinline__ void split2(float x, float y, uint32_t& hi, uint32_t& lo) {
    __nv_bfloat162 h = __floats2bfloat162_rn(x, y);
    float hx = __bfloat162float(h.x);
    float hy = __bfloat162float(h.y);
    __nv_bfloat162 l = __floats2bfloat162_rn(x - hx, y - hy);
    hi = *reinterpret_cast<uint32_t*>(&h);
    lo = *reinterpret_cast<uint32_t*>(&l);
}

// ---------------------------------------------------------------------------
// NT GEMM core (tensor cores, bf16x3):
//   C[row0..+128, col0..+128] = alpha * A(M,K) @ B(N,K)^T (+bias)
// A,B row-major, K contiguous. K = nstages*32. 256 threads.
// ---------------------------------------------------------------------------
__device__ __forceinline__ void gemm_nt_core(
    const float* __restrict__ A, int lda,
    const float* __restrict__ B, int ldb,
    float* __restrict__ C, int ldc,
    int nstages, float alpha, const float* __restrict__ bias,
    int row0, int col0)
{
    __shared__ __align__(16) __nv_bfloat16 sAh[128*PITCH];
    __shared__ __align__(16) __nv_bfloat16 sAl[128*PITCH];
    __shared__ __align__(16) __nv_bfloat16 sBh[128*PITCH];
    __shared__ __align__(16) __nv_bfloat16 sBl[128*PITCH];

    const int tid = threadIdx.x;
    const int w = tid >> 5, ln = tid & 31;
    const int wm = (w >> 2) * 64;     // warp m-offset (2 warps in m)
    const int wn = (w & 3) * 32;      // warp n-offset (4 warps in n)
    const int rg = tid >> 3;          // 0..31 load row group
    const int ck = tid & 7;           // 0..7 float4 chunk within 32-wide row

    const float* Ab = A + (size_t)(row0 + rg) * lda + ck * 4;
    const float* Bb = B + (size_t)(col0 + rg) * ldb + ck * 4;

    float acc[4][4][4];
#pragma unroll
    for (int i = 0; i < 4; i++)
#pragma unroll
        for (int j = 0; j < 4; j++)
#pragma unroll
            for (int t = 0; t < 4; t++) acc[i][j][t] = 0.f;

    const uint32_t uAh = cvta_s(sAh), uAl = cvta_s(sAl);
    const uint32_t uBh = cvta_s(sBh), uBl = cvta_s(sBl);

    float4 ar[4], br[4];
#pragma unroll
    for (int i = 0; i < 4; i++) {
        ar[i] = *(const float4*)(Ab + (size_t)i * 32 * lda);
        br[i] = *(const float4*)(Bb + (size_t)i * 32 * ldb);
    }

    for (int s = 0; s < nstages; s++) {
        // store current regs to smem (split hi/lo)
#pragma unroll
        for (int i = 0; i < 4; i++) {
            int r = rg + 32 * i;
            uint32_t h0, l0, h1, l1;
            split2(ar[i].x, ar[i].y, h0, l0);
            split2(ar[i].z, ar[i].w, h1, l1);
            int off = r * PITCH + ck * 4;
            *reinterpret_cast<uint32_t*>(&sAh[off])     = h0;
            *reinterpret_cast<uint32_t*>(&sAh[off + 2]) = h1;
            *reinterpret_cast<uint32_t*>(&sAl[off])     = l0;
            *reinterpret_cast<uint32_t*>(&sAl[off + 2]) = l1;
            split2(br[i].x, br[i].y, h0, l0);
            split2(br[i].z, br[i].w, h1, l1);
            *reinterpret_cast<uint32_t*>(&sBh[off])     = h0;
            *reinterpret_cast<uint32_t*>(&sBh[off + 2]) = h1;
            *reinterpret_cast<uint32_t*>(&sBl[off])     = l0;
            *reinterpret_cast<uint32_t*>(&sBl[off + 2]) = l1;
        }
        __syncthreads();

        // prefetch next stage
        if (s + 1 < nstages) {
            const float* An = Ab + (size_t)(s + 1) * 32;
            const float* Bn = Bb + (size_t)(s + 1) * 32;
#pragma unroll
            for (int i = 0; i < 4; i++) {
                ar[i] = *(const float4*)(An + (size_t)i * 32 * lda);
                br[i] = *(const float4*)(Bn + (size_t)i * 32 * ldb);
            }
        }

        // compute on smem stage
#pragma unroll
        for (int ks = 0; ks < 2; ks++) {
            uint32_t ah[4][4], al[4][4], bh[2][4], bl[2][4];
#pragma unroll
            for (int i = 0; i < 4; i++) {
                uint32_t off = (uint32_t)((wm + i * 16 + (ln & 15)) * PITCH) * 2
                             + (uint32_t)ks * 32 + (uint32_t)(ln >> 4) * 16;
                ldsm4(ah[i], uAh + off);
                ldsm4(al[i], uAl + off);
            }
#pragma unroll
            for (int g = 0; g < 2; g++) {
                uint32_t row = (uint32_t)(wn + g * 16 + ((ln >> 4) << 3) + (ln & 7));
                uint32_t off = row * PITCH * 2 + (uint32_t)ks * 32
                             + (uint32_t)((ln >> 3) & 1) * 16;
                ldsm4(bh[g], uBh + off);
                ldsm4(bl[g], uBl + off);
            }
#pragma unroll
            for (int i = 0; i < 4; i++)
#pragma unroll
                for (int j = 0; j < 4; j++) {
                    const uint32_t* bhj = &bh[j >> 1][(j & 1) * 2];
                    const uint32_t* blj = &bl[j >> 1][(j & 1) * 2];
                    mma_bf16(acc[i][j], ah[i], bhj);
                    mma_bf16(acc[i][j], ah[i], blj);
                    mma_bf16(acc[i][j], al[i], bhj);
                }
        }
        __syncthreads();
    }

    // epilogue
#pragma unroll
    for (int i = 0; i < 4; i++) {
        int r = row0 + wm + i * 16 + (ln >> 2);
#pragma unroll
        for (int j = 0; j < 4; j++) {
            int c = col0 + wn + j * 8 + 2 * (ln & 3);
            float b0 = 0.f, b1 = 0.f;
            if (bias) { b0 = bias[c]; b1 = bias[c + 1]; }
            float2 v0 = make_float2(fmaf(alpha, acc[i][j][0], b0),
                                    fmaf(alpha, acc[i][j][1], b1));
            float2 v1 = make_float2(fmaf(alpha, acc[i][j][2], b0),
                                    fmaf(alpha, acc[i][j][3], b1));
            *(float2*)&C[(size_t)r * ldc + c] = v0;
            *(float2*)&C[(size_t)(r + 8) * ldc + c] = v1;
        }
    }
}

// ---------------------------------------------------------------------------
// Projections: qp = q @ Wq^T + bq  (z selects q/k/v)
// ---------------------------------------------------------------------------
__global__ void __launch_bounds__(256, 1) proj_mma_kernel(
    const float* __restrict__ q, const float* __restrict__ k, const float* __restrict__ v,
    const float* __restrict__ Wq, const float* __restrict__ bq,
    const float* __restrict__ Wk, const float* __restrict__ bk,
    const float* __restrict__ Wv, const float* __restrict__ bv)
{
    const float *X, *W, *bias; float* O;
    if (blockIdx.z == 0)      { X = q; W = Wq; bias = bq; O = g_qp; }
    else if (blockIdx.z == 1) { X = k; W = Wk; bias = bk; O = g_kp; }
    else                      { X = v; W = Wv; bias = bv; O = g_vp; }
    gemm_nt_core(X, DMODEL, W, DMODEL, O, DMODEL, DMODEL / 32, 1.f, bias,
                 blockIdx.y * 128, blockIdx.x * 128);
}

// ---------------------------------------------------------------------------
// Scores: S[b,h] = (qh @ kh^T) / 8 → attention region of d_out
// ---------------------------------------------------------------------------
__global__ void __launch_bounds__(256, 1) scores_mma_kernel(float* __restrict__ att)
{
    int z = blockIdx.z;             // b*16 + h
    int b = z >> 4, h = z & 15;
    const float* A  = g_qp + (size_t)b * SEQ * DMODEL + h * HD;
    const float* Bm = g_kp + (size_t)b * SEQ * DMODEL + h * HD;
    float* Cz = att + (size_t)z * SEQ * SEQ;
    gemm_nt_core(A, DMODEL, Bm, DMODEL, Cz, SEQ, HD / 32, 0.125f, nullptr,
                 blockIdx.y * 128, blockIdx.x * 128);
}

// ---------------------------------------------------------------------------
// Row softmax, in place on the attention buffer. Mask applied (-inf).
// ---------------------------------------------------------------------------
__global__ void softmax_kernel(float* __restrict__ att,
                               const unsigned char* __restrict__ masks)
{
    __shared__ float red[8];
    __shared__ float bval;

    int row = blockIdx.x;
    int b = row >> 14;
    int i = row & (SEQ - 1);
    float* p = att + (size_t)row * SEQ;
    const unsigned char* mrow = masks + ((size_t)b * SEQ + i) * SEQ;

    int j = threadIdx.x * 4;
    float4 s = *(const float4*)(p + j);
    uchar4 m = *(const uchar4*)(mrow + j);
    float v0 = m.x ? -INFINITY : s.x;
    float v1 = m.y ? -INFINITY : s.y;
    float v2 = m.z ? -INFINITY : s.z;
    float v3 = m.w ? -INFINITY : s.w;

    float mx = fmaxf(fmaxf(v0, v1), fmaxf(v2, v3));
#pragma unroll
    for (int o = 16; o; o >>= 1) mx = fmaxf(mx, __shfl_xor_sync(0xffffffffu, mx, o));
    if ((threadIdx.x & 31) == 0) red[threadIdx.x >> 5] = mx;
    __syncthreads();
    if (threadIdx.x == 0) {
        float t = red[0];
#pragma unroll
        for (int w = 1; w < 8; w++) t = fmaxf(t, red[w]);
        bval = t;
    }
    __syncthreads();
    float rowmax = bval;

    float e0 = expf(v0 - rowmax);
    float e1 = expf(v1 - rowmax);
    float e2 = expf(v2 - rowmax);
    float e3 = expf(v3 - rowmax);

    float sm = e0 + e1 + e2 + e3;
#pragma unroll
    for (int o = 16; o; o >>= 1) sm += __shfl_xor_sync(0xffffffffu, sm, o);
    __syncthreads();
    if ((threadIdx.x & 31) == 0) red[threadIdx.x >> 5] = sm;
    __syncthreads();
    if (threadIdx.x == 0) {
        float t = 0.f;
#pragma unroll
        for (int w = 0; w < 8; w++) t += red[w];
        bval = 1.0f / t;
    }
    __syncthreads();
    float inv = bval;

    float4 r = make_float4(e0 * inv, e1 * inv, e2 * inv, e3 * inv);
    *(float4*)(p + j) = r;
}

// ---------------------------------------------------------------------------
// AV (NN GEMM, tensor cores): ctx[b,:,h] = att[b,h] @ vh[b,h]
// M=1024 (CTA 128), N=64, K=1024 (BK=32). 256 threads, warps 4(m) x 2(n).
// ---------------------------------------------------------------------------
__global__ void __launch_bounds__(256, 1) av_mma_kernel(const float* __restrict__ att)
{
    __shared__ __align__(16) __nv_bfloat16 sAh[128*PITCH];
    __shared__ __align__(16) __nv_bfloat16 sAl[128*PITCH];
    __shared__ __align__(16) __nv_bfloat16 sVh[32*PITCHV];
    __shared__ __align__(16) __nv_bfloat16 sVl[32*PITCHV];

    int z = blockIdx.z;
    int b = z >> 4, h = z & 15;
    const float* A = att + (size_t)z * SEQ * SEQ;                    // [1024,1024]
    const float* V = g_vp + (size_t)b * SEQ * DMODEL + h * HD;       // rows k, n contig
    float* C = g_ctx + (size_t)b * SEQ * DMODEL + h * HD;
    const int row0 = blockIdx.y * 128;

    const int tid = threadIdx.x;
    const int w = tid >> 5, ln = tid & 31;
    const int wm = (w >> 1) * 32;     // 4 warps in m
    const int wn = (w & 1) * 32;      // 2 warps in n
    const int rg = tid >> 3, ck = tid & 7;          // A loader
    const int vr = tid >> 4, vc = tid & 15;         // V loader: 16 rows x 16 chunks

    const float* Ab = A + (size_t)(row0 + rg) * SEQ + ck * 4;
    const float* Vb = V + (size_t)vr * DMODEL + vc * 4;

    float acc[2][4][4];
#pragma unroll
    for (int i = 0; i < 2; i++)
#pragma unroll
        for (int j = 0; j < 4; j++)
#pragma unroll
            for (int t = 0; t < 4; t++) acc[i][j][t] = 0.f;

    const uint32_t uAh = cvta_s(sAh), uAl = cvta_s(sAl);
    const uint32_t uVh = cvta_s(sVh), uVl = cvta_s(sVl);

    float4 ar[4], vrg[2];
#pragma unroll
    for (int i = 0; i < 4; i++) ar[i] = *(const float4*)(Ab + (size_t)i * 32 * SEQ);
#pragma unroll
    for (int i = 0; i < 2; i++) vrg[i] = *(const float4*)(Vb + (size_t)i * 16 * DMODEL);

    const int NSTAGES = SEQ / 32;
    for (int s = 0; s < NSTAGES; s++) {
#pragma unroll
        for (int i = 0; i < 4; i++) {
            int r = rg + 32 * i;
            uint32_t h0, l0, h1, l1;
            split2(ar[i].x, ar[i].y, h0, l0);
            split2(ar[i].z, ar[i].w, h1, l1);
            int off = r * PITCH + ck * 4;
            *reinterpret_cast<uint32_t*>(&sAh[off])     = h0;
            *reinterpret_cast<uint32_t*>(&sAh[off + 2]) = h1;
            *reinterpret_cast<uint32_t*>(&sAl[off])     = l0;
            *reinterpret_cast<uint32_t*>(&sAl[off + 2]) = l1;
        }
#pragma unroll
        for (int i = 0; i < 2; i++) {
            int r = vr + 16 * i;
            uint32_t h0, l0, h1, l1;
            split2(vrg[i].x, vrg[i].y, h0, l0);
            split2(vrg[i].z, vrg[i].w, h1, l1);
            int off = r * PITCHV + vc * 4;
            *reinterpret_cast<uint32_t*>(&sVh[off])     = h0;
            *reinterpret_cast<uint32_t*>(&sVh[off + 2]) = h1;
            *reinterpret_cast<uint32_t*>(&sVl[off])     = l0;
            *reinterpret_cast<uint32_t*>(&sVl[off + 2]) = l1;
        }
        __syncthreads();

        if (s + 1 < NSTAGES) {
            const float* An = Ab + (size_t)(s + 1) * 32;
            const float* Vn = Vb + (size_t)(s + 1) * 32 * DMODEL;
#pragma unroll
            for (int i = 0; i < 4; i++) ar[i] = *(const float4*)(An + (size_t)i * 32 * SEQ);
#pragma unroll
            for (int i = 0; i < 2; i++) vrg[i] = *(const float4*)(Vn + (size_t)i * 16 * DMODEL);
        }

#pragma unroll
        for (int ks = 0; ks < 2; ks++) {
            uint32_t ah[2][4], al[2][4], bh[2][4], bl[2][4];
#pragma unroll
            for (int i = 0; i < 2; i++) {
                uint32_t off = (uint32_t)((wm + i * 16 + (ln & 15)) * PITCH) * 2
                             + (uint32_t)ks * 32 + (uint32_t)(ln >> 4) * 16;
                ldsm4(ah[i], uAh + off);
                ldsm4(al[i], uAl + off);
            }
#pragma unroll
            for (int g = 0; g < 2; g++) {
                // trans load: addresses are k-rows, data n-contiguous
                uint32_t rk = (uint32_t)(ks * 16 + (((ln >> 3) & 1) << 3) + (ln & 7));
                uint32_t nc = (uint32_t)(wn + g * 16 + ((ln >> 4) << 3));
                uint32_t off = rk * PITCHV * 2 + nc * 2;
                ldsm4t(bh[g], uVh + off);
                ldsm4t(bl[g], uVl + off);
            }
#pragma unroll
            for (int i = 0; i < 2; i++)
#pragma unroll
                for (int j = 0; j < 4; j++) {
                    const uint32_t* bhj = &bh[j >> 1][(j & 1) * 2];
                    const uint32_t* blj = &bl[j >> 1][(j & 1) * 2];
                    mma_bf16(acc[i][j], ah[i], bhj);
                    mma_bf16(acc[i][j], ah[i], blj);
                    mma_bf16(acc[i][j], al[i], bhj);
                }
        }
        __syncthreads();
    }

#pragma unroll
    for (int i = 0; i < 2; i++) {
        int r = row0 + wm + i * 16 + (ln >> 2);
#pragma unroll
        for (int j = 0; j < 4; j++) {
            int c = wn + j * 8 + 2 * (ln & 3);
            *(float2*)&C[(size_t)r * DMODEL + c] =
                make_float2(acc[i][j][0], acc[i][j][1]);
            *(float2*)&C[(size_t)(r + 8) * DMODEL + c] =
                make_float2(acc[i][j][2], acc[i][j][3]);
        }
    }
}

// ---------------------------------------------------------------------------
// output = LayerNorm(qp + ctx) * g + b
// ---------------------------------------------------------------------------
__global__ void ln_kernel(float* __restrict__ out,
                          const float* __restrict__ gam,
                          const float* __restrict__ bet)
{
    __shared__ float reds[8];
    __shared__ float redq[8];
    __shared__ float stat[2];

    int row = blockIdx.x;
    const float* xq = g_qp + (size_t)row * DMODEL;
    const float* xc = g_ctx + (size_t)row * DMODEL;
    int j = threadIdx.x * 4;

    float4 a = *(const float4*)(xq + j);
    float4 c = *(const float4*)(xc + j);
    float x0 = a.x + c.x, x1 = a.y + c.y, x2 = a.z + c.z, x3 = a.w + c.w;

    float s = x0 + x1 + x2 + x3;
    float sq = x0 * x0 + x1 * x1 + x2 * x2 + x3 * x3;
#pragma unroll
    for (int o = 16; o; o >>= 1) {
        s += __shfl_xor_sync(0xffffffffu, s, o);
        sq += __shfl_xor_sync(0xffffffffu, sq, o);
    }
    if ((threadIdx.x & 31) == 0) { reds[threadIdx.x >> 5] = s; redq[threadIdx.x >> 5] = sq; }
    __syncthreads();
    if (threadIdx.x == 0) {
        float S = 0.f, Q = 0.f;
#pragma unroll
        for (int w = 0; w < 8; w++) { S += reds[w]; Q += redq[w]; }
        float mu = S * (1.0f / DMODEL);
        float var = Q * (1.0f / DMODEL) - mu * mu;
        stat[0] = mu;
        stat[1] = rsqrtf(var + 1e-6f);
    }
    __syncthreads();
    float mu = stat[0], r = stat[1];

    float4 g4 = *(const float4*)(gam + j);
    float4 b4 = *(const float4*)(bet + j);
    float4 o4;
    o4.x = (x0 - mu) * r * g4.x + b4.x;
    o4.y = (x1 - mu) * r * g4.y + b4.y;
    o4.z = (x2 - mu) * r * g4.z + b4.z;
    o4.w = (x3 - mu) * r * g4.w + b4.w;
    *(float4*)(out + (size_t)row * DMODEL + j) = o4;
}

// ---------------------------------------------------------------------------
extern "C" void kernel_launch(void* const* d_in, const int* in_sizes, int n_in,
                              void* d_out, int out_size)
{
    const float* q  = (const float*)d_in[0];
    const float* k  = (const float*)d_in[1];
    const float* v  = (const float*)d_in[2];
    const unsigned char* masks = (const unsigned char*)d_in[3];
    const float* Wq = (const float*)d_in[4];
    const float* bq = (const float*)d_in[5];
    const float* Wk = (const float*)d_in[6];
    const float* bk = (const float*)d_in[7];
    const float* Wv = (const float*)d_in[8];
    const float* bv = (const float*)d_in[9];
    const float* lng = (const float*)d_in[10];
    const float* lnb = (const float*)d_in[11];

    float* out = (float*)d_out;
    float* att = out + (size_t)BATCH * SEQ * DMODEL;

    proj_mma_kernel<<<dim3(DMODEL / 128, NROWS / 128, 3), 256>>>(
        q, k, v, Wq, bq, Wk, bk, Wv, bv);
    scores_mma_kernel<<<dim3(SEQ / 128, SEQ / 128, BATCH * NH), 256>>>(att);
    softmax_kernel<<<BATCH * NH * SEQ, 256>>>(att, masks);
    av_mma_kernel<<<dim3(1, SEQ / 128, BATCH * NH), 256>>>(att);
    ln_kernel<<<NROWS, 256>>>(out, lng, lnb);
}